// round 16
// baseline (speedup 1.0000x reference)
#include <cuda_runtime.h>
#include <math.h>

#define BSZ 4
#define DCH 256
#define HC 128
#define WC 128
#define RH 64
#define RW 64
#define RAD 3
#define S2 49
#define CIN0 52
#define HID 32
#define NPIX (HC*WC)
#define NCHK 64            // 64 chunks of 4 channels

// scratch (static device globals; no runtime allocation)
__device__ float g_q[BSZ*NCHK*NPIX*4];   // packed [b][chunk][p][4]
__device__ float g_k[BSZ*NCHK*NPIX*4];   // packed [b][chunk][p][4]
__device__ float g_x[BSZ*CIN0*NPIX];     // conv input, planar NCHW
__device__ float g_h1[BSZ*HID*NPIX];
__device__ float g_h2[BSZ*HID*NPIX];
__device__ __align__(16) float g_w0T2[CIN0*25*64];  // w0 transposed+DUPLICATED [cin][tap][oc dup pairs]
__device__ __align__(16) float g_w1T2[HID*25*64];   // w1 transposed+DUPLICATED

__device__ __forceinline__ float wsum32(float v){
#pragma unroll
    for (int o = 16; o; o >>= 1) v += __shfl_xor_sync(0xffffffffu, v, o);
    return v;
}

// ---------------- K0: transpose + duplicate conv weights [cin][tap][{w,w}x32] --
__global__ __launch_bounds__(256) void k_wprep(const float* __restrict__ w0,
                                               const float* __restrict__ w1){
    int i = blockIdx.x*256 + threadIdx.x;
    if (i < CIN0*25*32){
        int ic = i / 800; int rem = i % 800;
        int tap = rem >> 5, oc = rem & 31;
        float v = w0[(oc*CIN0 + ic)*25 + tap];
        ((float2*)g_w0T2)[i] = make_float2(v, v);
    }
    int j = i - CIN0*25*32;
    if (j >= 0 && j < HID*25*32){
        int ic = j / 800; int rem = j % 800;
        int tap = rem >> 5, oc = rem & 31;
        float v = w1[(oc*HID + ic)*25 + tap];
        ((float2*)g_w1T2)[j] = make_float2(v, v);
    }
}

// ---------------- K1: bilinear upsample 64->128 (half-pixel) + L2 normalize ----
__global__ __launch_bounds__(256) void k_qprep(const float* __restrict__ rubin){
    int gw = (blockIdx.x*blockDim.x + threadIdx.x) >> 5;
    int lane = threadIdx.x & 31;
    if (gw >= BSZ*NPIX) return;
    int b = gw / NPIX, p = gw % NPIX, y = p / WC, x = p % WC;
    float sy = 0.5f*y - 0.25f, sx = 0.5f*x - 0.25f;
    int y0 = (int)floorf(sy), x0 = (int)floorf(sx);
    float fy = sy - (float)y0, fx = sx - (float)x0;
    int y0c = max(y0, 0), y1c = min(y0+1, RH-1);
    int x0c = max(x0, 0), x1c = min(x0+1, RW-1);
    float w00 = (1.f-fy)*(1.f-fx), w01 = (1.f-fy)*fx, w10 = fy*(1.f-fx), w11 = fy*fx;
    const float* base = rubin + (size_t)b*RH*RW*DCH;
    const float* t00 = base + ((size_t)(y0c*RW + x0c))*DCH + lane*8;
    const float* t01 = base + ((size_t)(y0c*RW + x1c))*DCH + lane*8;
    const float* t10 = base + ((size_t)(y1c*RW + x0c))*DCH + lane*8;
    const float* t11 = base + ((size_t)(y1c*RW + x1c))*DCH + lane*8;
    float4 a0 = *(const float4*)t00, a1 = *(const float4*)(t00+4);
    float4 b0 = *(const float4*)t01, b1 = *(const float4*)(t01+4);
    float4 c0 = *(const float4*)t10, c1 = *(const float4*)(t10+4);
    float4 d0 = *(const float4*)t11, d1 = *(const float4*)(t11+4);
    float v[8];
    v[0] = w00*a0.x + w01*b0.x + w10*c0.x + w11*d0.x;
    v[1] = w00*a0.y + w01*b0.y + w10*c0.y + w11*d0.y;
    v[2] = w00*a0.z + w01*b0.z + w10*c0.z + w11*d0.z;
    v[3] = w00*a0.w + w01*b0.w + w10*c0.w + w11*d0.w;
    v[4] = w00*a1.x + w01*b1.x + w10*c1.x + w11*d1.x;
    v[5] = w00*a1.y + w01*b1.y + w10*c1.y + w11*d1.y;
    v[6] = w00*a1.z + w01*b1.z + w10*c1.z + w11*d1.z;
    v[7] = w00*a1.w + w01*b1.w + w10*c1.w + w11*d1.w;
    float ss = 0.f;
#pragma unroll
    for (int j = 0; j < 8; j++) ss += v[j]*v[j];
    ss = wsum32(ss);
    float inv = 1.f / fmaxf(sqrtf(ss), 1e-12f);
    int c0i = lane*2;
    float4* o0 = (float4*)(g_q + (((size_t)b*NCHK + c0i    )*NPIX + p)*4);
    float4* o1 = (float4*)(g_q + (((size_t)b*NCHK + c0i + 1)*NPIX + p)*4);
    *o0 = make_float4(v[0]*inv, v[1]*inv, v[2]*inv, v[3]*inv);
    *o1 = make_float4(v[4]*inv, v[5]*inv, v[6]*inv, v[7]*inv);
}

// ---------------- K2: L2 normalize vis tokens, packed layout -------------------
__global__ __launch_bounds__(256) void k_kprep(const float* __restrict__ vis){
    int gw = (blockIdx.x*blockDim.x + threadIdx.x) >> 5;
    int lane = threadIdx.x & 31;
    if (gw >= BSZ*NPIX) return;
    int b = gw / NPIX, p = gw % NPIX;
    const float* t = vis + (size_t)gw*DCH + lane*8;
    float4 a0 = *(const float4*)t, a1 = *(const float4*)(t+4);
    float ss = a0.x*a0.x + a0.y*a0.y + a0.z*a0.z + a0.w*a0.w
             + a1.x*a1.x + a1.y*a1.y + a1.z*a1.z + a1.w*a1.w;
    ss = wsum32(ss);
    float inv = 1.f / fmaxf(sqrtf(ss), 1e-12f);
    int c0i = lane*2;
    float4* o0 = (float4*)(g_k + (((size_t)b*NCHK + c0i    )*NPIX + p)*4);
    float4* o1 = (float4*)(g_k + (((size_t)b*NCHK + c0i + 1)*NPIX + p)*4);
    *o0 = make_float4(a0.x*inv, a0.y*inv, a0.z*inv, a0.w*inv);
    *o1 = make_float4(a1.x*inv, a1.y*inv, a1.z*inv, a1.w*inv);
}

// ---------------- K3: correlation + fused soft-argmax, cp.async RING-3 ---------
// (unchanged from R14: 119.6us, L1 73.7%)
__global__ __launch_bounds__(256, 2) void k_corr(const float* __restrict__ log_temp,
                                                 float* __restrict__ out){
    extern __shared__ __align__(16) float4 sk3[];   // [3][2][7][128] = 86016B
    int t = threadIdx.x;
    int b = blockIdx.x >> 7;
    int y = blockIdx.x & 127;
    int half = t >> 7;                    // 0 or 1
    int x = t & 127;

    const float4* kbase = (const float4*)g_k + (size_t)b*NCHK*NPIX;
    const float4* qbase = (const float4*)g_q + ((size_t)b*NCHK + half*32)*NPIX;

    int rows[7];
#pragma unroll
    for (int s = 0; s < 7; s++) rows[s] = min(max(y - 3 + s, 0), HC-1);
    int xxc[7];
#pragma unroll
    for (int d = 0; d < 7; d++) xxc[d] = min(max(x + d - 3, 0), WC-1);
    int hh_[7], ssl_[7], jj_[7];
#pragma unroll
    for (int i = 0; i < 7; i++){
        int e = t + i*256;
        hh_[i] = e / 896;
        int rem = e - hh_[i]*896;
        ssl_[i] = rem >> 7; jj_[i] = rem & 127;
    }
    unsigned int sbase = (unsigned int)__cvta_generic_to_shared(sk3);

    float acc[S2];
#pragma unroll
    for (int o = 0; o < S2; o++) acc[o] = 0.f;

    auto issue = [&](int c, int st){
#pragma unroll
        for (int i = 0; i < 7; i++){
            unsigned int sa = sbase + (unsigned int)((st*1792 + hh_[i]*896 + ssl_[i]*128 + jj_[i])*16);
            const float4* ga = kbase + (size_t)(hh_[i]*32 + c)*NPIX + rows[ssl_[i]]*WC + jj_[i];
            asm volatile("cp.async.cg.shared.global [%0], [%1], 16;" :: "r"(sa), "l"(ga));
        }
    };

    issue(0, 0);
    asm volatile("cp.async.commit_group;");
    issue(1, 1);
    asm volatile("cp.async.commit_group;");
    float4 qc = qbase[y*WC + x];

    int st = 0;
#pragma unroll 1
    for (int c = 0; c < 32; c++){
        asm volatile("cp.async.wait_group 1;");
        __syncthreads();
        int nst = st + 2; if (nst >= 3) nst -= 3;
        if (c + 2 < 32) issue(c + 2, nst);
        asm volatile("cp.async.commit_group;");
        float4 nq;
        if (c + 1 < 32) nq = qbase[(size_t)(c+1)*NPIX + y*WC + x];
        const float4* sp = sk3 + st*1792 + half*896;
#pragma unroll
        for (int dy = 0; dy < 7; dy++){
#pragma unroll
            for (int dx = 0; dx < 7; dx++){
                float4 k4 = sp[dy*128 + xxc[dx]];
                acc[dy*7+dx] += qc.x*k4.x + qc.y*k4.y + qc.z*k4.z + qc.w*k4.w;
            }
        }
        if (c + 1 < 32) qc = nq;
        if (++st == 3) st = 0;
    }
    asm volatile("cp.async.wait_group 0;");

    __syncthreads();
    float* s_red = (float*)sk3;
    if (half == 1){
#pragma unroll
        for (int o = 0; o < S2; o++) s_red[o*128 + x] = acc[o];
    }
    __syncthreads();
    if (half == 0){
#pragma unroll
        for (int o = 0; o < S2; o++) acc[o] += s_red[o*128 + x];

        int p = y*WC + x;
        float* xb = g_x + (size_t)b*CIN0*NPIX;
#pragma unroll
        for (int o = 0; o < S2; o++) xb[(size_t)(2+o)*NPIX + p] = acc[o];

        float m = -1e30f;
#pragma unroll
        for (int o = 0; o < S2; o++) m = fmaxf(m, acc[o]);
        float it = expf(-log_temp[0]);   // 1/temp
        float ssum = 0.f, sy = 0.f, sx = 0.f, em = 0.f;
#pragma unroll
        for (int o = 0; o < S2; o++){
            float e = expf((acc[o] - m) * it);
            ssum += e;
            em = fmaxf(em, e);
            sy += e * (float)(o/7 - 3);
            sx += e * (float)(o%7 - 3);
        }
        float inv = 1.f / ssum;
        float dyv = sy*inv, dxv = sx*inv, conf = em*inv;
        xb[p] = dyv;
        xb[(size_t)NPIX + p] = dxv;
        xb[51*(size_t)NPIX + p] = conf;
        size_t ob = (size_t)b*5*NPIX;
        out[ob + 2*(size_t)NPIX + p] = dyv;
        out[ob + 3*(size_t)NPIX + p] = dxv;
        out[ob + 4*(size_t)NPIX + p] = conf;
    }
}

// ---------------- conv 5x5, COUT=32: column-pair f32x2, dup weights ------------
// Thread handles 2 adjacent output columns (packed f32x2), 4 rows, 4 oc.
// Input staged as TWO copies (offset 0 and +1 float) so every tap's pair is an
// aligned LDS.64. Weights pre-duplicated {w,w} -> LDS.128 broadcast, NO splats.
// Inner body per (icl,kx): 8 LDS.64 + 10 LDS.128 + 80 FFMA2.
// Tile 64x4 px; 2 teams x 256 thr (cin split); ICCH=2; cp.async ring-2.
#define ICCH2   2
#define IN_ROW  68
#define SIN_BYTES (ICCH2*2*8*IN_ROW*4)        // 8704
#define SW_BYTES  (ICCH2*25*64*4)             // 12800
#define TEAM_STAGE_B (SIN_BYTES + SW_BYTES)   // 21504

template<int CIN>
__device__ __forceinline__ void conv_issue(char* smx, int team, int slot, int t,
                                           int b, int x0, int y0, int cb, bool act,
                                           const float* in, const float* wtT2){
    if (act){
        unsigned int sa = (unsigned int)__cvta_generic_to_shared(
                              smx + (team*2 + slot)*TEAM_STAGE_B);
        // input: 2 icl x 2 copies x 8 rows x 68 cols, 4B copies, zero-fill OOB
        for (int e = t; e < ICCH2*2*8*IN_ROW; e += 256){
            int icl = e / (2*8*IN_ROW); int rem = e % (2*8*IN_ROW);
            int cp = rem / (8*IN_ROW);  int rem2 = rem % (8*IN_ROW);
            int ry = rem2 / IN_ROW, rx = rem2 % IN_ROW;
            int gy = y0 - 2 + ry, gx = x0 - 2 + cp + rx;
            bool ok = (gy >= 0 && gy < HC && gx >= 0 && gx < WC);
            const float* src = in + (((size_t)b*CIN + cb + icl)*HC + (ok?gy:0))*WC + (ok?gx:0);
            int sz = ok ? 4 : 0;
            asm volatile("cp.async.ca.shared.global [%0], [%1], 4, %2;"
                         :: "r"(sa + e*4), "l"(src), "r"(sz));
        }
        // weights (duplicated): 2 icl x 25 tap x 64 floats = 800 float4, contiguous
        unsigned int sw = sa + SIN_BYTES;
        const float4* wsrc = (const float4*)(wtT2 + (size_t)cb*25*64);
        for (int e = t; e < 800; e += 256){
            asm volatile("cp.async.cg.shared.global [%0], [%1], 16;"
                         :: "r"(sw + e*16), "l"(wsrc + e));
        }
    }
}

template<int CIN, bool DOGELU>
__global__ __launch_bounds__(512, 2) void k_conv32(const float* __restrict__ in,
                                                   float* __restrict__ out,
                                                   const float* __restrict__ wtT2,
                                                   const float* __restrict__ bs){
    extern __shared__ __align__(16) char smx[];
    int tid = threadIdx.x;
    int team = tid >> 8;
    int t = tid & 255;
    int tx = t & 31;                 // column-pair: cols x0+2tx, x0+2tx+1
    int z  = t >> 5;                 // oc group z*4..z*4+3
    int x0 = blockIdx.x*64, y0 = blockIdx.y*4, b = blockIdx.z;

    const int H0  = (CIN == 52) ? 28 : 16;
    const int NIT = (CIN == 52) ? 14 : 8;     // per-team iterations (2 ch each)
    int clo = team ? H0 : 0;
    int chi = team ? CIN : H0;

    unsigned long long acc2[4][4];   // [oc][row], f32x2 = {col 2tx, col 2tx+1}
#pragma unroll
    for (int i = 0; i < 4; i++)
#pragma unroll
        for (int j = 0; j < 4; j++) acc2[i][j] = 0ull;

    // prologue: stage iters 0 and 1
    conv_issue<CIN>(smx, team, 0, t, b, x0, y0, clo,         clo         < chi, in, wtT2);
    asm volatile("cp.async.commit_group;");
    conv_issue<CIN>(smx, team, 1, t, b, x0, y0, clo + ICCH2, clo + ICCH2 < chi, in, wtT2);
    asm volatile("cp.async.commit_group;");

#pragma unroll 1
    for (int it = 0; it < NIT; it++){
        asm volatile("cp.async.wait_group 1;");
        __syncthreads();
        int slot = it & 1;
        int cb = clo + it*ICCH2;
        if (cb < chi){
            const float* s_base = (const float*)(smx + (team*2 + slot)*TEAM_STAGE_B);
            const float* s_w    = s_base + SIN_BYTES/4;
#pragma unroll 1
            for (int icl = 0; icl < ICCH2; icl++){
#pragma unroll
                for (int kx = 0; kx < 5; kx++){
                    int cp = kx & 1;
                    int col = 2*tx + kx - cp;        // even -> 8B aligned
                    const float* rowp = s_base + icl*(2*8*IN_ROW) + cp*(8*IN_ROW) + col;
                    unsigned long long F[8];
#pragma unroll
                    for (int r = 0; r < 8; r++)
                        F[r] = *(const unsigned long long*)(rowp + r*IN_ROW);
#pragma unroll
                    for (int ky = 0; ky < 5; ky++){
                        int tap = ky*5 + kx;
                        const ulonglong2* wp = (const ulonglong2*)(s_w + (icl*25 + tap)*64 + z*8);
                        ulonglong2 wa = wp[0];   // {w0,w0},{w1,w1}
                        ulonglong2 wb = wp[1];   // {w2,w2},{w3,w3}
#pragma unroll
                        for (int rr = 0; rr < 4; rr++){
                            asm("fma.rn.f32x2 %0, %1, %2, %0;"
                                : "+l"(acc2[0][rr]) : "l"(F[rr+ky]), "l"(wa.x));
                            asm("fma.rn.f32x2 %0, %1, %2, %0;"
                                : "+l"(acc2[1][rr]) : "l"(F[rr+ky]), "l"(wa.y));
                            asm("fma.rn.f32x2 %0, %1, %2, %0;"
                                : "+l"(acc2[2][rr]) : "l"(F[rr+ky]), "l"(wb.x));
                            asm("fma.rn.f32x2 %0, %1, %2, %0;"
                                : "+l"(acc2[3][rr]) : "l"(F[rr+ky]), "l"(wb.y));
                        }
                    }
                }
            }
        }
        __syncthreads();
        int cbn = clo + (it+2)*ICCH2;
        conv_issue<CIN>(smx, team, it & 1, t, b, x0, y0, cbn, cbn < chi, in, wtT2);
        asm volatile("cp.async.commit_group;");
    }

    // drain pending copies, then merge team partials through reused smem
    asm volatile("cp.async.wait_group 0;");
    __syncthreads();
    unsigned long long* s_red = (unsigned long long*)smx;
    if (team == 1){
#pragma unroll
        for (int j = 0; j < 4; j++)
#pragma unroll
            for (int rr = 0; rr < 4; rr++)
                s_red[(j*4 + rr)*256 + t] = acc2[j][rr];
    }
    __syncthreads();
    if (team == 0){
#pragma unroll
        for (int j = 0; j < 4; j++)
#pragma unroll
            for (int rr = 0; rr < 4; rr++){
                unsigned long long o = s_red[(j*4 + rr)*256 + t];
                asm("add.rn.f32x2 %0, %0, %1;" : "+l"(acc2[j][rr]) : "l"(o));
            }
#pragma unroll
        for (int j = 0; j < 4; j++){
            int oc = z*4 + j;
            float bb = bs[oc];
#pragma unroll
            for (int rr = 0; rr < 4; rr++){
                float lo, hi;
                asm("mov.b64 {%0,%1}, %2;" : "=f"(lo), "=f"(hi) : "l"(acc2[j][rr]));
                float v0 = lo + bb, v1 = hi + bb;
                if (DOGELU){
                    v0 = 0.5f*v0*(1.f + erff(v0*0.7071067811865476f));
                    v1 = 0.5f*v1*(1.f + erff(v1*0.7071067811865476f));
                }
                *(float2*)&out[(((size_t)b*32 + oc)*HC + y0 + rr)*WC + x0 + 2*tx]
                    = make_float2(v0, v1);
            }
        }
    }
}

// ---------------- conv2 (32->2) + compose final output -------------------------
__global__ __launch_bounds__(256) void k_conv2_final(const float* __restrict__ h,
                                                     const float* __restrict__ wt,
                                                     const float* __restrict__ bs,
                                                     float* __restrict__ out){
    const int ICCH = 8;
    __shared__ float s_in[ICCH][12][36];
    __shared__ float s_w[HID][25][2];
    int tx = threadIdx.x & 31;
    int z  = threadIdx.x >> 5;
    int x0 = blockIdx.x*32, y0 = blockIdx.y*8, b = blockIdx.z;

    for (int e = threadIdx.x; e < HID*25*2; e += 256){
        int oc = e & 1; int rem = e >> 1;
        int tap = rem % 25; int ic = rem / 25;
        s_w[ic][tap][oc] = wt[((size_t)oc*HID + ic)*25 + tap];
    }

    float a0 = 0.f, a1 = 0.f;
#pragma unroll 1
    for (int cb = 0; cb < HID; cb += ICCH){
        __syncthreads();
        for (int e = threadIdx.x; e < ICCH*12*36; e += 256){
            int icl = e / (12*36); int rem = e % (12*36);
            int ry = rem / 36, rx = rem % 36;
            int gy = y0 - 2 + ry, gx = x0 - 2 + rx;
            float val = 0.f;
            if (gy >= 0 && gy < HC && gx >= 0 && gx < WC)
                val = h[(((size_t)b*HID + cb + icl)*HC + gy)*WC + gx];
            s_in[icl][ry][rx] = val;
        }
        __syncthreads();
#pragma unroll 1
        for (int icl = 0; icl < ICCH; icl++){
            int ic = cb + icl;
#pragma unroll
            for (int ky = 0; ky < 5; ky++){
#pragma unroll
                for (int kx = 0; kx < 5; kx++){
                    float2 wv = *(const float2*)&s_w[ic][ky*5+kx][0];
                    float v = s_in[icl][z+ky][tx+kx];
                    a0 += wv.x * v;
                    a1 += wv.y * v;
                }
            }
        }
    }
    int y = y0 + z, x = x0 + tx, p = y*WC + x;
    float r0 = a0 + bs[0];   // residual for dy (channel 0)
    float r1 = a1 + bs[1];   // residual for dx (channel 1)
    size_t xb = (size_t)b*CIN0*NPIX;
    float raw_dy = g_x[xb + 0*NPIX + p];
    float raw_dx = g_x[xb + 1*NPIX + p];
    const float sky = 1.6f;  // 2048 * 0.1 / 128
    size_t ob = (size_t)b*5*NPIX;
    out[ob + 0*(size_t)NPIX + p] = (raw_dx + r1) * sky;  // dra
    out[ob + 1*(size_t)NPIX + p] = (raw_dy + r0) * sky;  // ddec
}

extern "C" void kernel_launch(void* const* d_in, const int* in_sizes, int n_in,
                              void* d_out, int out_size){
    const float* rubin = (const float*)d_in[0];
    const float* vis   = (const float*)d_in[1];
    const float* w0    = (const float*)d_in[2];
    const float* b0    = (const float*)d_in[3];
    const float* w1    = (const float*)d_in[4];
    const float* b1    = (const float*)d_in[5];
    const float* w2    = (const float*)d_in[6];
    const float* b2    = (const float*)d_in[7];
    const float* lt    = (const float*)d_in[8];
    float* out = (float*)d_out;

    float *p_x, *p_h1, *p_h2, *p_w0T2, *p_w1T2;
    cudaGetSymbolAddress((void**)&p_x,    g_x);
    cudaGetSymbolAddress((void**)&p_h1,   g_h1);
    cudaGetSymbolAddress((void**)&p_h2,   g_h2);
    cudaGetSymbolAddress((void**)&p_w0T2, g_w0T2);
    cudaGetSymbolAddress((void**)&p_w1T2, g_w1T2);

    const int CONV_SMEM = 2*2*TEAM_STAGE_B;   // 86016
    const int CORR_SMEM = 3*2*7*128*16;       // 86016
    cudaFuncSetAttribute(k_conv32<CIN0, true>,
                         cudaFuncAttributeMaxDynamicSharedMemorySize, CONV_SMEM);
    cudaFuncSetAttribute(k_conv32<HID, true>,
                         cudaFuncAttributeMaxDynamicSharedMemorySize, CONV_SMEM);
    cudaFuncSetAttribute(k_corr,
                         cudaFuncAttributeMaxDynamicSharedMemorySize, CORR_SMEM);

    int nwarps = BSZ*NPIX;              // 65536 warps for preps
    k_wprep<<<((CIN0+HID)*25*32 + 255)/256, 256>>>(w0, w1);
    k_qprep<<<nwarps/8, 256>>>(rubin);
    k_kprep<<<nwarps/8, 256>>>(vis);

    k_corr<<<BSZ*128, 256, CORR_SMEM>>>(lt, out);  // 512 blocks, ring-3

    dim3 g(WC/64, HC/4, BSZ);           // (2,32,4) = 256 blocks, 512 threads
    k_conv32<CIN0, true><<<g, 512, CONV_SMEM>>>(p_x,  p_h1, p_w0T2, b0);
    k_conv32<HID,  true><<<g, 512, CONV_SMEM>>>(p_h1, p_h2, p_w1T2, b1);

    dim3 g2(WC/32, HC/8, BSZ);          // (4,16,4)
    k_conv2_final<<<g2, 256>>>(p_h2, w2, b2, out);
}

// round 17
// speedup vs baseline: 1.1554x; 1.1554x over previous
#include <cuda_runtime.h>
#include <math.h>

#define BSZ 4
#define DCH 256
#define HC 128
#define WC 128
#define RH 64
#define RW 64
#define RAD 3
#define S2 49
#define CIN0 52
#define HID 32
#define NPIX (HC*WC)
#define NCHK 64            // 64 chunks of 4 channels

// scratch (static device globals; no runtime allocation)
__device__ float g_q[BSZ*NCHK*NPIX*4];   // packed [b][chunk][p][4]
__device__ float g_k[BSZ*NCHK*NPIX*4];   // packed [b][chunk][p][4]
__device__ float g_x[BSZ*CIN0*NPIX];     // conv input, planar NCHW
__device__ float g_h1[BSZ*HID*NPIX];
__device__ float g_h2[BSZ*HID*NPIX];
__device__ __align__(16) float g_w0T[CIN0*25*32];  // w0 transposed [cin][tap][oc]
__device__ __align__(16) float g_w1T[HID*25*32];   // w1 transposed [cin][tap][oc]

__device__ __forceinline__ float wsum32(float v){
#pragma unroll
    for (int o = 16; o; o >>= 1) v += __shfl_xor_sync(0xffffffffu, v, o);
    return v;
}

// ---------------- K1 (fused): qprep | kprep | wprep, partitioned by blockIdx ---
// blocks [0, 8192)      : bilinear upsample 64->128 + L2-norm of rubin -> g_q
// blocks [8192, 16384)  : L2-norm of vis -> g_k
// blocks [16384, 16647) : weight transpose w0,w1 -> g_w0T, g_w1T
#define QP_BLOCKS (BSZ*NPIX/8)        // 8192
#define WP_BLOCKS (((CIN0+HID)*25*32 + 255)/256)   // 263

__global__ __launch_bounds__(256) void k_prep(const float* __restrict__ rubin,
                                              const float* __restrict__ vis,
                                              const float* __restrict__ w0,
                                              const float* __restrict__ w1){
    int blk = blockIdx.x;
    if (blk < QP_BLOCKS){
        int gw = (blk*256 + threadIdx.x) >> 5;
        int lane = threadIdx.x & 31;
        int b = gw / NPIX, p = gw % NPIX, y = p / WC, x = p % WC;
        float sy = 0.5f*y - 0.25f, sx = 0.5f*x - 0.25f;
        int y0 = (int)floorf(sy), x0 = (int)floorf(sx);
        float fy = sy - (float)y0, fx = sx - (float)x0;
        int y0c = max(y0, 0), y1c = min(y0+1, RH-1);
        int x0c = max(x0, 0), x1c = min(x0+1, RW-1);
        float w00 = (1.f-fy)*(1.f-fx), w01 = (1.f-fy)*fx, w10 = fy*(1.f-fx), w11 = fy*fx;
        const float* base = rubin + (size_t)b*RH*RW*DCH;
        const float* t00 = base + ((size_t)(y0c*RW + x0c))*DCH + lane*8;
        const float* t01 = base + ((size_t)(y0c*RW + x1c))*DCH + lane*8;
        const float* t10 = base + ((size_t)(y1c*RW + x0c))*DCH + lane*8;
        const float* t11 = base + ((size_t)(y1c*RW + x1c))*DCH + lane*8;
        float4 a0 = *(const float4*)t00, a1 = *(const float4*)(t00+4);
        float4 b0 = *(const float4*)t01, b1 = *(const float4*)(t01+4);
        float4 c0 = *(const float4*)t10, c1 = *(const float4*)(t10+4);
        float4 d0 = *(const float4*)t11, d1 = *(const float4*)(t11+4);
        float v[8];
        v[0] = w00*a0.x + w01*b0.x + w10*c0.x + w11*d0.x;
        v[1] = w00*a0.y + w01*b0.y + w10*c0.y + w11*d0.y;
        v[2] = w00*a0.z + w01*b0.z + w10*c0.z + w11*d0.z;
        v[3] = w00*a0.w + w01*b0.w + w10*c0.w + w11*d0.w;
        v[4] = w00*a1.x + w01*b1.x + w10*c1.x + w11*d1.x;
        v[5] = w00*a1.y + w01*b1.y + w10*c1.y + w11*d1.y;
        v[6] = w00*a1.z + w01*b1.z + w10*c1.z + w11*d1.z;
        v[7] = w00*a1.w + w01*b1.w + w10*c1.w + w11*d1.w;
        float ss = 0.f;
#pragma unroll
        for (int j = 0; j < 8; j++) ss += v[j]*v[j];
        ss = wsum32(ss);
        float inv = 1.f / fmaxf(sqrtf(ss), 1e-12f);
        int c0i = lane*2;
        float4* o0 = (float4*)(g_q + (((size_t)b*NCHK + c0i    )*NPIX + p)*4);
        float4* o1 = (float4*)(g_q + (((size_t)b*NCHK + c0i + 1)*NPIX + p)*4);
        *o0 = make_float4(v[0]*inv, v[1]*inv, v[2]*inv, v[3]*inv);
        *o1 = make_float4(v[4]*inv, v[5]*inv, v[6]*inv, v[7]*inv);
    } else if (blk < 2*QP_BLOCKS){
        int gw = ((blk - QP_BLOCKS)*256 + threadIdx.x) >> 5;
        int lane = threadIdx.x & 31;
        int b = gw / NPIX, p = gw % NPIX;
        const float* t = vis + (size_t)gw*DCH + lane*8;
        float4 a0 = *(const float4*)t, a1 = *(const float4*)(t+4);
        float ss = a0.x*a0.x + a0.y*a0.y + a0.z*a0.z + a0.w*a0.w
                 + a1.x*a1.x + a1.y*a1.y + a1.z*a1.z + a1.w*a1.w;
        ss = wsum32(ss);
        float inv = 1.f / fmaxf(sqrtf(ss), 1e-12f);
        int c0i = lane*2;
        float4* o0 = (float4*)(g_k + (((size_t)b*NCHK + c0i    )*NPIX + p)*4);
        float4* o1 = (float4*)(g_k + (((size_t)b*NCHK + c0i + 1)*NPIX + p)*4);
        *o0 = make_float4(a0.x*inv, a0.y*inv, a0.z*inv, a0.w*inv);
        *o1 = make_float4(a1.x*inv, a1.y*inv, a1.z*inv, a1.w*inv);
    } else {
        int i = (blk - 2*QP_BLOCKS)*256 + threadIdx.x;
        if (i < CIN0*25*32){
            int ic = i / 800; int rem = i % 800;
            int tap = rem >> 5, oc = rem & 31;
            g_w0T[i] = w0[(oc*CIN0 + ic)*25 + tap];
        }
        int j = i - CIN0*25*32;
        if (j >= 0 && j < HID*25*32){
            int ic = j / 800; int rem = j % 800;
            int tap = rem >> 5, oc = rem & 31;
            g_w1T[j] = w1[(oc*HID + ic)*25 + tap];
        }
    }
}

// ---------------- K3: correlation + fused soft-argmax, cp.async RING-3 ---------
// (R14-exact: 119.6us, L1 73.7%)
__global__ __launch_bounds__(256, 2) void k_corr(const float* __restrict__ log_temp,
                                                 float* __restrict__ out){
    extern __shared__ __align__(16) float4 sk3[];   // [3][2][7][128] = 86016B
    int t = threadIdx.x;
    int b = blockIdx.x >> 7;
    int y = blockIdx.x & 127;
    int half = t >> 7;                    // 0 or 1
    int x = t & 127;

    const float4* kbase = (const float4*)g_k + (size_t)b*NCHK*NPIX;
    const float4* qbase = (const float4*)g_q + ((size_t)b*NCHK + half*32)*NPIX;

    int rows[7];
#pragma unroll
    for (int s = 0; s < 7; s++) rows[s] = min(max(y - 3 + s, 0), HC-1);
    int xxc[7];
#pragma unroll
    for (int d = 0; d < 7; d++) xxc[d] = min(max(x + d - 3, 0), WC-1);
    int hh_[7], ssl_[7], jj_[7];
#pragma unroll
    for (int i = 0; i < 7; i++){
        int e = t + i*256;
        hh_[i] = e / 896;
        int rem = e - hh_[i]*896;
        ssl_[i] = rem >> 7; jj_[i] = rem & 127;
    }
    unsigned int sbase = (unsigned int)__cvta_generic_to_shared(sk3);

    float acc[S2];
#pragma unroll
    for (int o = 0; o < S2; o++) acc[o] = 0.f;

    auto issue = [&](int c, int st){
#pragma unroll
        for (int i = 0; i < 7; i++){
            unsigned int sa = sbase + (unsigned int)((st*1792 + hh_[i]*896 + ssl_[i]*128 + jj_[i])*16);
            const float4* ga = kbase + (size_t)(hh_[i]*32 + c)*NPIX + rows[ssl_[i]]*WC + jj_[i];
            asm volatile("cp.async.cg.shared.global [%0], [%1], 16;" :: "r"(sa), "l"(ga));
        }
    };

    issue(0, 0);
    asm volatile("cp.async.commit_group;");
    issue(1, 1);
    asm volatile("cp.async.commit_group;");
    float4 qc = qbase[y*WC + x];

    int st = 0;
#pragma unroll 1
    for (int c = 0; c < 32; c++){
        asm volatile("cp.async.wait_group 1;");
        __syncthreads();
        int nst = st + 2; if (nst >= 3) nst -= 3;
        if (c + 2 < 32) issue(c + 2, nst);
        asm volatile("cp.async.commit_group;");
        float4 nq;
        if (c + 1 < 32) nq = qbase[(size_t)(c+1)*NPIX + y*WC + x];
        const float4* sp = sk3 + st*1792 + half*896;
#pragma unroll
        for (int dy = 0; dy < 7; dy++){
#pragma unroll
            for (int dx = 0; dx < 7; dx++){
                float4 k4 = sp[dy*128 + xxc[dx]];
                acc[dy*7+dx] += qc.x*k4.x + qc.y*k4.y + qc.z*k4.z + qc.w*k4.w;
            }
        }
        if (c + 1 < 32) qc = nq;
        if (++st == 3) st = 0;
    }
    asm volatile("cp.async.wait_group 0;");

    __syncthreads();
    float* s_red = (float*)sk3;
    if (half == 1){
#pragma unroll
        for (int o = 0; o < S2; o++) s_red[o*128 + x] = acc[o];
    }
    __syncthreads();
    if (half == 0){
#pragma unroll
        for (int o = 0; o < S2; o++) acc[o] += s_red[o*128 + x];

        int p = y*WC + x;
        float* xb = g_x + (size_t)b*CIN0*NPIX;
#pragma unroll
        for (int o = 0; o < S2; o++) xb[(size_t)(2+o)*NPIX + p] = acc[o];

        float m = -1e30f;
#pragma unroll
        for (int o = 0; o < S2; o++) m = fmaxf(m, acc[o]);
        float it = expf(-log_temp[0]);   // 1/temp
        float ssum = 0.f, sy = 0.f, sx = 0.f, em = 0.f;
#pragma unroll
        for (int o = 0; o < S2; o++){
            float e = expf((acc[o] - m) * it);
            ssum += e;
            em = fmaxf(em, e);
            sy += e * (float)(o/7 - 3);
            sx += e * (float)(o%7 - 3);
        }
        float inv = 1.f / ssum;
        float dyv = sy*inv, dxv = sx*inv, conf = em*inv;
        xb[p] = dyv;
        xb[(size_t)NPIX + p] = dxv;
        xb[51*(size_t)NPIX + p] = conf;
        size_t ob = (size_t)b*5*NPIX;
        out[ob + 2*(size_t)NPIX + p] = dyv;
        out[ob + 3*(size_t)NPIX + p] = dxv;
        out[ob + 4*(size_t)NPIX + p] = conf;
    }
}

// ---------------- conv 5x5, COUT=32, 2-team 512-thread, cp.async ring-2 --------
// (R14-exact conv: transposed coalesced weights, ICCH=4, ring-2)
#define TEAM_STAGE_B 19712
#define SIN_BYTES    6912

template<int CIN>
__device__ __forceinline__ void conv_issue(char* smx, int team, int slot, int t,
                                           int b, int x0, int y0, int cb, bool act,
                                           const float* in, const float* wtT){
    if (act){
        unsigned int sa = (unsigned int)__cvta_generic_to_shared(
                              smx + (team*2 + slot)*TEAM_STAGE_B);
        // input: 4 icl x 12 rows x 36 cols, 4B copies, zero-fill OOB
        for (int e = t; e < 4*12*36; e += 256){
            int icl = e / 432; int rem = e % 432;
            int ry = rem / 36, rx = rem % 36;
            int gy = y0 - 2 + ry, gx = x0 - 2 + rx;
            bool ok = (gy >= 0 && gy < HC && gx >= 0 && gx < WC);
            const float* src = in + (((size_t)b*CIN + cb + icl)*HC + (ok?gy:0))*WC + (ok?gx:0);
            int sz = ok ? 4 : 0;
            asm volatile("cp.async.ca.shared.global [%0], [%1], 4, %2;"
                         :: "r"(sa + e*4), "l"(src), "r"(sz));
        }
        // weights: 4 icl x 25 tap x 32 oc = 800 float4, contiguous
        unsigned int sw = sa + SIN_BYTES;
        const float4* wsrc = (const float4*)(wtT + (size_t)cb*800);
        for (int e = t; e < 800; e += 256){
            asm volatile("cp.async.cg.shared.global [%0], [%1], 16;"
                         :: "r"(sw + e*16), "l"(wsrc + e));
        }
    }
}

template<int CIN, bool DOGELU>
__global__ __launch_bounds__(512, 2) void k_conv32(const float* __restrict__ in,
                                                   float* __restrict__ out,
                                                   const float* __restrict__ wtT,
                                                   const float* __restrict__ bs){
    extern __shared__ __align__(16) char smx[];
    int tid = threadIdx.x;
    int team = tid >> 8;
    int t = tid & 255;
    int tx = t & 31;
    int z  = t >> 5;
    int x0 = blockIdx.x*32, y0 = blockIdx.y*8, b = blockIdx.z;

    const int H0  = (CIN == 52) ? 28 : 16;
    const int NIT = (CIN == 52) ? 7 : 4;
    int clo = team ? H0 : 0;
    int chi = team ? CIN : H0;

    unsigned long long acc2[2][8];   // [oc-pair][row], f32x2 packed
#pragma unroll
    for (int i = 0; i < 2; i++)
#pragma unroll
        for (int j = 0; j < 8; j++) acc2[i][j] = 0ull;

    // prologue: stage iters 0 and 1
    conv_issue<CIN>(smx, team, 0, t, b, x0, y0, clo,     clo     < chi, in, wtT);
    asm volatile("cp.async.commit_group;");
    conv_issue<CIN>(smx, team, 1, t, b, x0, y0, clo + 4, clo + 4 < chi, in, wtT);
    asm volatile("cp.async.commit_group;");

#pragma unroll 1
    for (int it = 0; it < NIT; it++){
        asm volatile("cp.async.wait_group 1;");
        __syncthreads();
        int slot = it & 1;
        int cb = clo + it*4;
        if (cb < chi){
            float (*s_in)[12][36] = (float (*)[12][36])(smx + (team*2 + slot)*TEAM_STAGE_B);
            float (*s_w)[25][32]  = (float (*)[25][32])(smx + (team*2 + slot)*TEAM_STAGE_B + SIN_BYTES);
#pragma unroll 1
            for (int icl = 0; icl < 4; icl++){
#pragma unroll
                for (int kx = 0; kx < 5; kx++){
                    unsigned long long sv[12];
#pragma unroll
                    for (int r = 0; r < 12; r++){
                        float v = s_in[icl][r][tx+kx];
                        asm("mov.b64 %0, {%1,%1};" : "=l"(sv[r]) : "f"(v));
                    }
#pragma unroll
                    for (int ky = 0; ky < 5; ky++){
                        ulonglong2 w2 = *(const ulonglong2*)&s_w[icl][ky*5+kx][z*4];
#pragma unroll
                        for (int yy = 0; yy < 8; yy++){
                            asm("fma.rn.f32x2 %0, %1, %2, %0;"
                                : "+l"(acc2[0][yy]) : "l"(sv[yy+ky]), "l"(w2.x));
                            asm("fma.rn.f32x2 %0, %1, %2, %0;"
                                : "+l"(acc2[1][yy]) : "l"(sv[yy+ky]), "l"(w2.y));
                        }
                    }
                }
            }
        }
        __syncthreads();
        int cbn = clo + (it+2)*4;
        conv_issue<CIN>(smx, team, slot, t, b, x0, y0, cbn, cbn < chi, in, wtT);
        asm volatile("cp.async.commit_group;");
    }

    // drain pending copies, then merge team partials through reused smem
    asm volatile("cp.async.wait_group 0;");
    __syncthreads();
    unsigned long long* s_red = (unsigned long long*)smx;
    if (team == 1){
#pragma unroll
        for (int j = 0; j < 2; j++)
#pragma unroll
            for (int yy = 0; yy < 8; yy++)
                s_red[(j*8 + yy)*256 + t] = acc2[j][yy];
    }
    __syncthreads();
    if (team == 0){
#pragma unroll
        for (int j = 0; j < 2; j++)
#pragma unroll
            for (int yy = 0; yy < 8; yy++){
                unsigned long long o = s_red[(j*8 + yy)*256 + t];
                asm("add.rn.f32x2 %0, %0, %1;" : "+l"(acc2[j][yy]) : "l"(o));
            }
#pragma unroll
        for (int j = 0; j < 2; j++){
            int oc0 = z*4 + j*2;
            float bb0 = bs[oc0], bb1 = bs[oc0+1];
#pragma unroll
            for (int yy = 0; yy < 8; yy++){
                float lo, hi;
                asm("mov.b64 {%0,%1}, %2;" : "=f"(lo), "=f"(hi) : "l"(acc2[j][yy]));
                float v0 = lo + bb0, v1 = hi + bb1;
                if (DOGELU){
                    v0 = 0.5f*v0*(1.f + erff(v0*0.7071067811865476f));
                    v1 = 0.5f*v1*(1.f + erff(v1*0.7071067811865476f));
                }
                out[(((size_t)b*32 + oc0  )*HC + y0 + yy)*WC + x0 + tx] = v0;
                out[(((size_t)b*32 + oc0+1)*HC + y0 + yy)*WC + x0 + tx] = v1;
            }
        }
    }
}

// ---------------- conv2 (32->2) + compose final output -------------------------
__global__ __launch_bounds__(256) void k_conv2_final(const float* __restrict__ h,
                                                     const float* __restrict__ wt,
                                                     const float* __restrict__ bs,
                                                     float* __restrict__ out){
    const int ICCH = 8;
    __shared__ float s_in[ICCH][12][36];
    __shared__ float s_w[HID][25][2];
    int tx = threadIdx.x & 31;
    int z  = threadIdx.x >> 5;
    int x0 = blockIdx.x*32, y0 = blockIdx.y*8, b = blockIdx.z;

    for (int e = threadIdx.x; e < HID*25*2; e += 256){
        int oc = e & 1; int rem = e >> 1;
        int tap = rem % 25; int ic = rem / 25;
        s_w[ic][tap][oc] = wt[((size_t)oc*HID + ic)*25 + tap];
    }

    float a0 = 0.f, a1 = 0.f;
#pragma unroll 1
    for (int cb = 0; cb < HID; cb += ICCH){
        __syncthreads();
        for (int e = threadIdx.x; e < ICCH*12*36; e += 256){
            int icl = e / (12*36); int rem = e % (12*36);
            int ry = rem / 36, rx = rem % 36;
            int gy = y0 - 2 + ry, gx = x0 - 2 + rx;
            float val = 0.f;
            if (gy >= 0 && gy < HC && gx >= 0 && gx < WC)
                val = h[(((size_t)b*HID + cb + icl)*HC + gy)*WC + gx];
            s_in[icl][ry][rx] = val;
        }
        __syncthreads();
#pragma unroll 1
        for (int icl = 0; icl < ICCH; icl++){
            int ic = cb + icl;
#pragma unroll
            for (int ky = 0; ky < 5; ky++){
#pragma unroll
                for (int kx = 0; kx < 5; kx++){
                    float2 wv = *(const float2*)&s_w[ic][ky*5+kx][0];
                    float v = s_in[icl][z+ky][tx+kx];
                    a0 += wv.x * v;
                    a1 += wv.y * v;
                }
            }
        }
    }
    int y = y0 + z, x = x0 + tx, p = y*WC + x;
    float r0 = a0 + bs[0];   // residual for dy (channel 0)
    float r1 = a1 + bs[1];   // residual for dx (channel 1)
    size_t xb = (size_t)b*CIN0*NPIX;
    float raw_dy = g_x[xb + 0*NPIX + p];
    float raw_dx = g_x[xb + 1*NPIX + p];
    const float sky = 1.6f;  // 2048 * 0.1 / 128
    size_t ob = (size_t)b*5*NPIX;
    out[ob + 0*(size_t)NPIX + p] = (raw_dx + r1) * sky;  // dra
    out[ob + 1*(size_t)NPIX + p] = (raw_dy + r0) * sky;  // ddec
}

extern "C" void kernel_launch(void* const* d_in, const int* in_sizes, int n_in,
                              void* d_out, int out_size){
    const float* rubin = (const float*)d_in[0];
    const float* vis   = (const float*)d_in[1];
    const float* w0    = (const float*)d_in[2];
    const float* b0    = (const float*)d_in[3];
    const float* w1    = (const float*)d_in[4];
    const float* b1    = (const float*)d_in[5];
    const float* w2    = (const float*)d_in[6];
    const float* b2    = (const float*)d_in[7];
    const float* lt    = (const float*)d_in[8];
    float* out = (float*)d_out;

    float *p_x, *p_h1, *p_h2, *p_w0T, *p_w1T;
    cudaGetSymbolAddress((void**)&p_x,   g_x);
    cudaGetSymbolAddress((void**)&p_h1,  g_h1);
    cudaGetSymbolAddress((void**)&p_h2,  g_h2);
    cudaGetSymbolAddress((void**)&p_w0T, g_w0T);
    cudaGetSymbolAddress((void**)&p_w1T, g_w1T);

    const int CONV_SMEM = 2*2*TEAM_STAGE_B;   // 78848
    const int CORR_SMEM = 3*2*7*128*16;       // 86016
    cudaFuncSetAttribute(k_conv32<CIN0, true>,
                         cudaFuncAttributeMaxDynamicSharedMemorySize, CONV_SMEM);
    cudaFuncSetAttribute(k_conv32<HID, true>,
                         cudaFuncAttributeMaxDynamicSharedMemorySize, CONV_SMEM);
    cudaFuncSetAttribute(k_corr,
                         cudaFuncAttributeMaxDynamicSharedMemorySize, CORR_SMEM);

    // fused prep: qprep (8192 blocks) | kprep (8192) | wprep (263)
    k_prep<<<2*QP_BLOCKS + WP_BLOCKS, 256>>>(rubin, vis, w0, w1);

    k_corr<<<BSZ*128, 256, CORR_SMEM>>>(lt, out);  // 512 blocks, ring-3

    dim3 g(WC/32, HC/8, BSZ);           // (4,16,4) = 256 blocks, 512 threads
    k_conv32<CIN0, true><<<g, 512, CONV_SMEM>>>(p_x,  p_h1, p_w0T, b0);
    k_conv32<HID,  true><<<g, 512, CONV_SMEM>>>(p_h1, p_h2, p_w1T, b1);

    dim3 g2(WC/32, HC/8, BSZ);          // (4,16,4)
    k_conv2_final<<<g2, 256>>>(p_h2, w2, b2, out);
}